// round 9
// baseline (speedup 1.0000x reference)
#include <cuda_runtime.h>
#include <cmath>
#include <vector>
#include <cstddef>

// Problem dimensions
#define LAT 512
#define BATCH 128
#define NROWS_SPECIAL 639   // rows 0..638 of bc contain all nonzero entries

// Constants computed on the host once (input-independent):
//   ddr[l] = Re( DFT_diag[l] * diag(inv(DFT))[l] )
//   dq[l]  = DFT_diag[l]  (entries in {-1,0,1} + i{-1,0,1})
struct ConstData {
    float ddr[LAT];
    float2 dq[LAT];
};

static ConstData g_cd;

// Side stream + events for the fork-join capture pattern. Created once at
// program load (host-side; no device allocations inside kernel_launch).
static cudaStream_t g_s2;
static cudaEvent_t g_evA, g_evB;
static struct StreamInit {
    StreamInit() {
        cudaStreamCreateWithFlags(&g_s2, cudaStreamNonBlocking);
        cudaEventCreateWithFlags(&g_evA, cudaEventDisableTiming);
        cudaEventCreateWithFlags(&g_evB, cudaEventDisableTiming);
    }
} g_sinit;

// ---------------------------------------------------------------------------
// Host-side static init: build the rounded DFT matrix, LU-factorize in double
// precision, extract diag(inv(M)). Pure CPU, once at load, off the timed path.
// ---------------------------------------------------------------------------
static struct ConstInit {
    ConstInit() {
        const int L = LAT;
        std::vector<double> Ar((size_t)L * L), Ai((size_t)L * L);
        std::vector<double> dgr(L), dgi(L);
        const double TWO_PI = 6.283185307179586476925286766559;
        for (int j = 0; j < L; j++) {
            for (int k = 0; k < L; k++) {
                int m = (j * k) % L;
                double ang = TWO_PI * (double)m / (double)L;
                Ar[(size_t)j * L + k] = std::round(std::cos(ang));
                Ai[(size_t)j * L + k] = std::round(std::sin(ang));
            }
            dgr[j] = Ar[(size_t)j * L + j];
            dgi[j] = Ai[(size_t)j * L + j];
        }

        // LU with partial pivoting (in place)
        std::vector<int> piv(L);
        for (int k = 0; k < L; k++) {
            int p = k;
            double best = Ar[(size_t)k * L + k] * Ar[(size_t)k * L + k] +
                          Ai[(size_t)k * L + k] * Ai[(size_t)k * L + k];
            for (int i = k + 1; i < L; i++) {
                double v = Ar[(size_t)i * L + k] * Ar[(size_t)i * L + k] +
                           Ai[(size_t)i * L + k] * Ai[(size_t)i * L + k];
                if (v > best) { best = v; p = i; }
            }
            piv[k] = p;
            if (p != k) {
                for (int j = 0; j < L; j++) {
                    double tr = Ar[(size_t)k * L + j], ti = Ai[(size_t)k * L + j];
                    Ar[(size_t)k * L + j] = Ar[(size_t)p * L + j];
                    Ai[(size_t)k * L + j] = Ai[(size_t)p * L + j];
                    Ar[(size_t)p * L + j] = tr;
                    Ai[(size_t)p * L + j] = ti;
                }
            }
            double akr = Ar[(size_t)k * L + k], aki = Ai[(size_t)k * L + k];
            double den = 1.0 / (akr * akr + aki * aki);
            const double* rkr = &Ar[(size_t)k * L];
            const double* rki = &Ai[(size_t)k * L];
            for (int i = k + 1; i < L; i++) {
                double* rir = &Ar[(size_t)i * L];
                double* rii = &Ai[(size_t)i * L];
                double xr = rir[k], xi = rii[k];
                double fr = (xr * akr + xi * aki) * den;
                double fi = (xi * akr - xr * aki) * den;
                rir[k] = fr; rii[k] = fi;
                for (int j = k + 1; j < L; j++) {
                    double br = rkr[j], bi = rki[j];
                    rir[j] -= fr * br - fi * bi;
                    rii[j] -= fr * bi + fi * br;
                }
            }
        }

        // diag(inv(M)): for each column c, solve M x = e_c, keep x[c]
        std::vector<double> xr(L), xi(L);
        for (int c = 0; c < L; c++) {
            for (int i = 0; i < L; i++) { xr[i] = (i == c) ? 1.0 : 0.0; xi[i] = 0.0; }
            for (int k = 0; k < L; k++) {
                if (piv[k] != k) {
                    double tr = xr[k], ti = xi[k];
                    xr[k] = xr[piv[k]]; xi[k] = xi[piv[k]];
                    xr[piv[k]] = tr;    xi[piv[k]] = ti;
                }
            }
            for (int i = 0; i < L; i++) {          // forward solve (unit lower)
                double sr = xr[i], si = xi[i];
                const double* rir = &Ar[(size_t)i * L];
                const double* rii = &Ai[(size_t)i * L];
                for (int j = 0; j < i; j++) {
                    sr -= rir[j] * xr[j] - rii[j] * xi[j];
                    si -= rir[j] * xi[j] + rii[j] * xr[j];
                }
                xr[i] = sr; xi[i] = si;
            }
            for (int i = L - 1; i >= 0; i--) {     // back solve
                double sr = xr[i], si = xi[i];
                const double* rir = &Ar[(size_t)i * L];
                const double* rii = &Ai[(size_t)i * L];
                for (int j = i + 1; j < L; j++) {
                    sr -= rir[j] * xr[j] - rii[j] * xi[j];
                    si -= rir[j] * xi[j] + rii[j] * xr[j];
                }
                double ur = rir[i], ui = rii[i];
                double den = 1.0 / (ur * ur + ui * ui);
                xr[i] = (sr * ur + si * ui) * den;
                xi[i] = (si * ur - sr * ui) * den;
            }
            // Re(dd[c]) = Re( diag[c] * dinv_diag[c] )
            g_cd.ddr[c] = (float)(dgr[c] * xr[c] - dgi[c] * xi[c]);
            g_cd.dq[c] = make_float2((float)dgr[c], (float)dgi[c]);
        }
    }
} g_init;

// ---------------------------------------------------------------------------
// Small kernel (runs CONCURRENTLY with the big memset; disjoint regions):
//   blocks 0..638   : write bc row r completely (zeros + its nonzero entry)
//   blocks 639..766 : write Y row b = blk-639
// One block per 512-float row; thread t owns float4 #t of the row.
// ---------------------------------------------------------------------------
__global__ void __launch_bounds__(128)
head_kernel(ConstData cd,
            const float* __restrict__ eig,
            const float* __restrict__ a_eps,
            const float* __restrict__ b_eps,
            float4* __restrict__ out4,
            size_t y4_off) {
    const int t = threadIdx.x;       // 0..127
    const int blk = blockIdx.x;      // 0..766
    const float* __restrict__ e127p = eig + (BATCH - 1) * LAT;

    if (blk < NROWS_SPECIAL) {
        float4 v = make_float4(0.f, 0.f, 0.f, 0.f);
        if (blk < BATCH - 1) {
            // Re(bc)[blk, 0] = ddr[0] * eig[blk, 0]
            if (t == 0) v.x = cd.ddr[0] * eig[blk * LAT];
        } else {
            // Re(bc)[127 + d, d] = ddr[d] * eig[127, d]
            const int d = blk - (BATCH - 1);
            if ((d >> 2) == t) {
                const float val = cd.ddr[d] * e127p[d];
                ((float*)&v)[d & 3] = val;
            }
        }
        out4[(size_t)blk * 128 + t] = v;
    } else {
        const int b = blk - NROWS_SPECIAL;   // 0..127
        const int l0 = t << 2;
        float4 v;
        #pragma unroll
        for (int k = 0; k < 4; k++) {
            const int l = l0 + k;
            const float2 q = cd.dq[l];
            ((float*)&v)[k] = sqrtf(e127p[l]) *
                (q.x * a_eps[l * BATCH + b] - q.y * b_eps[l * BATCH + b]);
        }
        out4[y4_off + (size_t)b * 128 + t] = v;
    }
}

extern "C" void kernel_launch(void* const* d_in, const int* in_sizes, int n_in,
                              void* d_out, int out_size) {
    const float* eig   = (const float*)d_in[0];  // eigenvalues (128, 512)
    const float* a_eps = (const float*)d_in[1];  // (512, 128)
    const float* b_eps = (const float*)d_in[2];  // (512, 128)
    float* out = (float*)d_out;

    // out_size = 33,619,968 float32 elements:
    //   [ Re(bc) : 65536*512 = 33,554,432 ][ Y : 128*512 = 65,536 ]
    const size_t y_floats = (size_t)BATCH * LAT;            // 65536
    const size_t y_off = (size_t)out_size - y_floats;       // 33,554,432
    const size_t zero_start = (size_t)NROWS_SPECIAL * LAT;  // 327,168 floats
    const size_t zero_bytes = (y_off - zero_start) * sizeof(float);  // ~132.9 MB

    // Fork: branch A (side stream) zeros rows 639.. (pure zeros, peak BW);
    //       branch B (capture stream) writes rows 0..638 + Y concurrently.
    // Regions are disjoint -> no ordering needed between the branches.
    cudaEventRecord(g_evA, 0);
    cudaStreamWaitEvent(g_s2, g_evA, 0);
    cudaMemsetAsync(out + zero_start, 0, zero_bytes, g_s2);

    head_kernel<<<NROWS_SPECIAL + BATCH, 128>>>(
        g_cd, eig, a_eps, b_eps, (float4*)out, y_off / 4);

    // Join: downstream (and graph end) depends on both branches.
    cudaEventRecord(g_evB, g_s2);
    cudaStreamWaitEvent((cudaStream_t)0, g_evB, 0);
}

// round 10
// speedup vs baseline: 1.1526x; 1.1526x over previous
#include <cuda_runtime.h>
#include <cmath>
#include <vector>
#include <cstddef>

// Problem dimensions
#define LAT 512
#define BATCH 128

// Grid plan: ONE kernel, ONE full wave on 148 SMs.
//   256 threads/block, 1184 blocks = 64 warps/SM exactly.
//   blocks [0, 320)     : special bc rows, 2 rows/block (rows 0..639)
//   blocks [320, 384)   : Y (128 x 512 floats = 16384 float4)
//   blocks [384, 1184)  : pure zero fill of bc rows 640..65535
#define SPECIAL_BLOCKS 320
#define Y_BLOCKS 64
#define FILL_BLOCKS 800
#define TOTAL_BLOCKS (SPECIAL_BLOCKS + Y_BLOCKS + FILL_BLOCKS)  // 1184
#define THREADS 256

// Constants computed on the host once (input-independent):
//   ddr[l] = Re( DFT_diag[l] * diag(inv(DFT))[l] )
//   dq[l]  = DFT_diag[l]  (entries in {-1,0,1} + i{-1,0,1})
struct ConstData {
    float ddr[LAT];
    float2 dq[LAT];
};

static ConstData g_cd;

// ---------------------------------------------------------------------------
// Host-side static init: build the rounded DFT matrix, LU-factorize in double
// precision, extract diag(inv(M)). Pure CPU, once at load, off the timed path.
// ---------------------------------------------------------------------------
static struct ConstInit {
    ConstInit() {
        const int L = LAT;
        std::vector<double> Ar((size_t)L * L), Ai((size_t)L * L);
        std::vector<double> dgr(L), dgi(L);
        const double TWO_PI = 6.283185307179586476925286766559;
        for (int j = 0; j < L; j++) {
            for (int k = 0; k < L; k++) {
                int m = (j * k) % L;
                double ang = TWO_PI * (double)m / (double)L;
                Ar[(size_t)j * L + k] = std::round(std::cos(ang));
                Ai[(size_t)j * L + k] = std::round(std::sin(ang));
            }
            dgr[j] = Ar[(size_t)j * L + j];
            dgi[j] = Ai[(size_t)j * L + j];
        }

        // LU with partial pivoting (in place)
        std::vector<int> piv(L);
        for (int k = 0; k < L; k++) {
            int p = k;
            double best = Ar[(size_t)k * L + k] * Ar[(size_t)k * L + k] +
                          Ai[(size_t)k * L + k] * Ai[(size_t)k * L + k];
            for (int i = k + 1; i < L; i++) {
                double v = Ar[(size_t)i * L + k] * Ar[(size_t)i * L + k] +
                           Ai[(size_t)i * L + k] * Ai[(size_t)i * L + k];
                if (v > best) { best = v; p = i; }
            }
            piv[k] = p;
            if (p != k) {
                for (int j = 0; j < L; j++) {
                    double tr = Ar[(size_t)k * L + j], ti = Ai[(size_t)k * L + j];
                    Ar[(size_t)k * L + j] = Ar[(size_t)p * L + j];
                    Ai[(size_t)k * L + j] = Ai[(size_t)p * L + j];
                    Ar[(size_t)p * L + j] = tr;
                    Ai[(size_t)p * L + j] = ti;
                }
            }
            double akr = Ar[(size_t)k * L + k], aki = Ai[(size_t)k * L + k];
            double den = 1.0 / (akr * akr + aki * aki);
            const double* rkr = &Ar[(size_t)k * L];
            const double* rki = &Ai[(size_t)k * L];
            for (int i = k + 1; i < L; i++) {
                double* rir = &Ar[(size_t)i * L];
                double* rii = &Ai[(size_t)i * L];
                double xr = rir[k], xi = rii[k];
                double fr = (xr * akr + xi * aki) * den;
                double fi = (xi * akr - xr * aki) * den;
                rir[k] = fr; rii[k] = fi;
                for (int j = k + 1; j < L; j++) {
                    double br = rkr[j], bi = rki[j];
                    rir[j] -= fr * br - fi * bi;
                    rii[j] -= fr * bi + fi * br;
                }
            }
        }

        // diag(inv(M)): for each column c, solve M x = e_c, keep x[c]
        std::vector<double> xr(L), xi(L);
        for (int c = 0; c < L; c++) {
            for (int i = 0; i < L; i++) { xr[i] = (i == c) ? 1.0 : 0.0; xi[i] = 0.0; }
            for (int k = 0; k < L; k++) {
                if (piv[k] != k) {
                    double tr = xr[k], ti = xi[k];
                    xr[k] = xr[piv[k]]; xi[k] = xi[piv[k]];
                    xr[piv[k]] = tr;    xi[piv[k]] = ti;
                }
            }
            for (int i = 0; i < L; i++) {          // forward solve (unit lower)
                double sr = xr[i], si = xi[i];
                const double* rir = &Ar[(size_t)i * L];
                const double* rii = &Ai[(size_t)i * L];
                for (int j = 0; j < i; j++) {
                    sr -= rir[j] * xr[j] - rii[j] * xi[j];
                    si -= rir[j] * xi[j] + rii[j] * xr[j];
                }
                xr[i] = sr; xi[i] = si;
            }
            for (int i = L - 1; i >= 0; i--) {     // back solve
                double sr = xr[i], si = xi[i];
                const double* rir = &Ar[(size_t)i * L];
                const double* rii = &Ai[(size_t)i * L];
                for (int j = i + 1; j < L; j++) {
                    sr -= rir[j] * xr[j] - rii[j] * xi[j];
                    si -= rir[j] * xi[j] + rii[j] * xr[j];
                }
                double ur = rir[i], ui = rii[i];
                double den = 1.0 / (ur * ur + ui * ui);
                xr[i] = (sr * ur + si * ui) * den;
                xi[i] = (si * ur - sr * ui) * den;
            }
            // Re(dd[c]) = Re( diag[c] * dinv_diag[c] )
            g_cd.ddr[c] = (float)(dgr[c] * xr[c] - dgi[c] * xi[c]);
            g_cd.dq[c] = make_float2((float)dgr[c], (float)dgi[c]);
        }
    }
} g_init;

// ---------------------------------------------------------------------------
// ONE kernel, branch decided per block. Fill blocks run a bare STG.128 loop
// (memset-class BW); special/Y blocks finish early, their SM partners keep
// DRAM saturated. Everything resident in a single wave.
// ---------------------------------------------------------------------------
__global__ void __launch_bounds__(THREADS)
fused_wave_kernel(ConstData cd,
                  const float* __restrict__ eig,
                  const float* __restrict__ a_eps,
                  const float* __restrict__ b_eps,
                  float4* __restrict__ out4,
                  size_t y4_off) {
    const int t = threadIdx.x;       // 0..255
    const int blk = blockIdx.x;      // 0..1183

    if (blk >= SPECIAL_BLOCKS + Y_BLOCKS) {
        // Pure zero fill of bc rows 640..65535: (65536-640)*128 float4.
        const size_t n4z = (size_t)(65536 - 2 * SPECIAL_BLOCKS) * 128;  // 8,306,688
        float4* __restrict__ z4 = out4 + (size_t)(2 * SPECIAL_BLOCKS) * 128;
        const float4 z = make_float4(0.f, 0.f, 0.f, 0.f);
        const size_t stride = (size_t)FILL_BLOCKS * THREADS;            // 204,800
        size_t i = (size_t)(blk - (SPECIAL_BLOCKS + Y_BLOCKS)) * THREADS + t;
        #pragma unroll 4
        for (; i < n4z; i += stride) z4[i] = z;
        return;
    }

    const float* __restrict__ e127p = eig + (BATCH - 1) * LAT;

    if (blk < SPECIAL_BLOCKS) {
        // Two special bc rows per block: rows 2*blk and 2*blk+1 (0..639).
        // Row 639 contains no nonzero entry and falls out naturally.
        const int r = 2 * blk + (t >> 7);     // row handled by this thread
        const int tr = t & 127;               // float4 index within the row
        float4 v = make_float4(0.f, 0.f, 0.f, 0.f);
        if (r < BATCH - 1) {
            // Re(bc)[r, 0] = ddr[0] * eig[r, 0]
            if (tr == 0) v.x = cd.ddr[0] * eig[r * LAT];
        } else {
            // Re(bc)[127 + d, d] = ddr[d] * eig[127, d]   (d in [0,512))
            const int d = r - (BATCH - 1);
            if ((d >> 2) == tr) {             // d<512 -> d>>2<128, matches one tr
                ((float*)&v)[d & 3] = cd.ddr[d] * e127p[d];
            }
        }
        out4[(size_t)r * 128 + tr] = v;
    } else {
        // Y: yi in [0, 16384) float4; Y[b, l] row-major, 128 float4 per row.
        const int yi = (blk - SPECIAL_BLOCKS) * THREADS + t;
        const int b = yi >> 7;                // 0..127
        const int l0 = (yi & 127) << 2;       // 0,4,...,508
        float4 v;
        #pragma unroll
        for (int k = 0; k < 4; k++) {
            const int l = l0 + k;
            const float2 q = cd.dq[l];
            ((float*)&v)[k] = sqrtf(e127p[l]) *
                (q.x * a_eps[l * BATCH + b] - q.y * b_eps[l * BATCH + b]);
        }
        out4[y4_off + (size_t)yi] = v;
    }
}

extern "C" void kernel_launch(void* const* d_in, const int* in_sizes, int n_in,
                              void* d_out, int out_size) {
    const float* eig   = (const float*)d_in[0];  // eigenvalues (128, 512)
    const float* a_eps = (const float*)d_in[1];  // (512, 128)
    const float* b_eps = (const float*)d_in[2];  // (512, 128)

    // out_size = 33,619,968 float32 elements:
    //   [ Re(bc) : 65536*512 = 33,554,432 ][ Y : 128*512 = 65,536 ]
    const size_t y_floats = (size_t)BATCH * LAT;          // 65536
    const size_t y_off = (size_t)out_size - y_floats;     // 33,554,432

    fused_wave_kernel<<<TOTAL_BLOCKS, THREADS>>>(
        g_cd, eig, a_eps, b_eps, (float4*)d_out, y_off / 4);
}

// round 11
// speedup vs baseline: 1.4691x; 1.2746x over previous
#include <cuda_runtime.h>
#include <cmath>
#include <vector>
#include <cstddef>

// Problem dimensions
#define LAT 512
#define BATCH 128
#define NROWS_SPECIAL 639   // rows 0..638 of bc contain all nonzero entries

// Constants computed on the host once (input-independent):
//   ddr[l] = Re( DFT_diag[l] * diag(inv(DFT))[l] )
//   dq[l]  = DFT_diag[l]  (entries in {-1,0,1} + i{-1,0,1})
struct ConstData {
    float ddr[LAT];
    float2 dq[LAT];
};

static ConstData g_cd;

// Side stream + events for the fork-join capture pattern. Created once at
// program load (host-side; no device allocations inside kernel_launch).
static cudaStream_t g_s2;
static cudaEvent_t g_evA, g_evB;
static struct StreamInit {
    StreamInit() {
        cudaStreamCreateWithFlags(&g_s2, cudaStreamNonBlocking);
        cudaEventCreateWithFlags(&g_evA, cudaEventDisableTiming);
        cudaEventCreateWithFlags(&g_evB, cudaEventDisableTiming);
    }
} g_sinit;

// ---------------------------------------------------------------------------
// Host-side static init: build the rounded DFT matrix, LU-factorize in double
// precision, extract diag(inv(M)). Pure CPU, once at load, off the timed path.
// ---------------------------------------------------------------------------
static struct ConstInit {
    ConstInit() {
        const int L = LAT;
        std::vector<double> Ar((size_t)L * L), Ai((size_t)L * L);
        std::vector<double> dgr(L), dgi(L);
        const double TWO_PI = 6.283185307179586476925286766559;
        for (int j = 0; j < L; j++) {
            for (int k = 0; k < L; k++) {
                int m = (j * k) % L;
                double ang = TWO_PI * (double)m / (double)L;
                Ar[(size_t)j * L + k] = std::round(std::cos(ang));
                Ai[(size_t)j * L + k] = std::round(std::sin(ang));
            }
            dgr[j] = Ar[(size_t)j * L + j];
            dgi[j] = Ai[(size_t)j * L + j];
        }

        // LU with partial pivoting (in place)
        std::vector<int> piv(L);
        for (int k = 0; k < L; k++) {
            int p = k;
            double best = Ar[(size_t)k * L + k] * Ar[(size_t)k * L + k] +
                          Ai[(size_t)k * L + k] * Ai[(size_t)k * L + k];
            for (int i = k + 1; i < L; i++) {
                double v = Ar[(size_t)i * L + k] * Ar[(size_t)i * L + k] +
                           Ai[(size_t)i * L + k] * Ai[(size_t)i * L + k];
                if (v > best) { best = v; p = i; }
            }
            piv[k] = p;
            if (p != k) {
                for (int j = 0; j < L; j++) {
                    double tr = Ar[(size_t)k * L + j], ti = Ai[(size_t)k * L + j];
                    Ar[(size_t)k * L + j] = Ar[(size_t)p * L + j];
                    Ai[(size_t)k * L + j] = Ai[(size_t)p * L + j];
                    Ar[(size_t)p * L + j] = tr;
                    Ai[(size_t)p * L + j] = ti;
                }
            }
            double akr = Ar[(size_t)k * L + k], aki = Ai[(size_t)k * L + k];
            double den = 1.0 / (akr * akr + aki * aki);
            const double* rkr = &Ar[(size_t)k * L];
            const double* rki = &Ai[(size_t)k * L];
            for (int i = k + 1; i < L; i++) {
                double* rir = &Ar[(size_t)i * L];
                double* rii = &Ai[(size_t)i * L];
                double xr = rir[k], xi = rii[k];
                double fr = (xr * akr + xi * aki) * den;
                double fi = (xi * akr - xr * aki) * den;
                rir[k] = fr; rii[k] = fi;
                for (int j = k + 1; j < L; j++) {
                    double br = rkr[j], bi = rki[j];
                    rir[j] -= fr * br - fi * bi;
                    rii[j] -= fr * bi + fi * br;
                }
            }
        }

        // diag(inv(M)): for each column c, solve M x = e_c, keep x[c]
        std::vector<double> xr(L), xi(L);
        for (int c = 0; c < L; c++) {
            for (int i = 0; i < L; i++) { xr[i] = (i == c) ? 1.0 : 0.0; xi[i] = 0.0; }
            for (int k = 0; k < L; k++) {
                if (piv[k] != k) {
                    double tr = xr[k], ti = xi[k];
                    xr[k] = xr[piv[k]]; xi[k] = xi[piv[k]];
                    xr[piv[k]] = tr;    xi[piv[k]] = ti;
                }
            }
            for (int i = 0; i < L; i++) {          // forward solve (unit lower)
                double sr = xr[i], si = xi[i];
                const double* rir = &Ar[(size_t)i * L];
                const double* rii = &Ai[(size_t)i * L];
                for (int j = 0; j < i; j++) {
                    sr -= rir[j] * xr[j] - rii[j] * xi[j];
                    si -= rir[j] * xi[j] + rii[j] * xr[j];
                }
                xr[i] = sr; xi[i] = si;
            }
            for (int i = L - 1; i >= 0; i--) {     // back solve
                double sr = xr[i], si = xi[i];
                const double* rir = &Ar[(size_t)i * L];
                const double* rii = &Ai[(size_t)i * L];
                for (int j = i + 1; j < L; j++) {
                    sr -= rir[j] * xr[j] - rii[j] * xi[j];
                    si -= rir[j] * xi[j] + rii[j] * xr[j];
                }
                double ur = rir[i], ui = rii[i];
                double den = 1.0 / (ur * ur + ui * ui);
                xr[i] = (sr * ur + si * ui) * den;
                xi[i] = (si * ur - sr * ui) * den;
            }
            // Re(dd[c]) = Re( diag[c] * dinv_diag[c] )
            g_cd.ddr[c] = (float)(dgr[c] * xr[c] - dgi[c] * xi[c]);
            g_cd.dq[c] = make_float2((float)dgr[c], (float)dgi[c]);
        }
    }
} g_init;

// ---------------------------------------------------------------------------
// Small kernel (runs CONCURRENTLY with the big memset; disjoint regions):
//   blocks 0..638   : write bc row r completely (zeros + its nonzero entry)
//   blocks 639..766 : write Y row b = blk-639
// One block per 512-float row; thread t owns float4 #t of the row.
// ---------------------------------------------------------------------------
__global__ void __launch_bounds__(128)
head_kernel(ConstData cd,
            const float* __restrict__ eig,
            const float* __restrict__ a_eps,
            const float* __restrict__ b_eps,
            float4* __restrict__ out4,
            size_t y4_off) {
    const int t = threadIdx.x;       // 0..127
    const int blk = blockIdx.x;      // 0..766
    const float* __restrict__ e127p = eig + (BATCH - 1) * LAT;

    if (blk < NROWS_SPECIAL) {
        float4 v = make_float4(0.f, 0.f, 0.f, 0.f);
        if (blk < BATCH - 1) {
            // Re(bc)[blk, 0] = ddr[0] * eig[blk, 0]
            if (t == 0) v.x = cd.ddr[0] * eig[blk * LAT];
        } else {
            // Re(bc)[127 + d, d] = ddr[d] * eig[127, d]
            const int d = blk - (BATCH - 1);
            if ((d >> 2) == t) {
                const float val = cd.ddr[d] * e127p[d];
                ((float*)&v)[d & 3] = val;
            }
        }
        out4[(size_t)blk * 128 + t] = v;
    } else {
        const int b = blk - NROWS_SPECIAL;   // 0..127
        const int l0 = t << 2;
        float4 v;
        #pragma unroll
        for (int k = 0; k < 4; k++) {
            const int l = l0 + k;
            const float2 q = cd.dq[l];
            ((float*)&v)[k] = sqrtf(e127p[l]) *
                (q.x * a_eps[l * BATCH + b] - q.y * b_eps[l * BATCH + b]);
        }
        out4[y4_off + (size_t)b * 128 + t] = v;
    }
}

extern "C" void kernel_launch(void* const* d_in, const int* in_sizes, int n_in,
                              void* d_out, int out_size) {
    const float* eig   = (const float*)d_in[0];  // eigenvalues (128, 512)
    const float* a_eps = (const float*)d_in[1];  // (512, 128)
    const float* b_eps = (const float*)d_in[2];  // (512, 128)
    float* out = (float*)d_out;

    // out_size = 33,619,968 float32 elements:
    //   [ Re(bc) : 65536*512 = 33,554,432 ][ Y : 128*512 = 65,536 ]
    const size_t y_floats = (size_t)BATCH * LAT;            // 65536
    const size_t y_off = (size_t)out_size - y_floats;       // 33,554,432
    const size_t zero_start = (size_t)NROWS_SPECIAL * LAT;  // 327,168 floats
    const size_t zero_bytes = (y_off - zero_start) * sizeof(float);  // ~132.9 MB

    // Fork: branch A (side stream) zeros rows 639.. (pure zeros, peak BW);
    //       branch B (capture stream) writes rows 0..638 + Y concurrently.
    // Regions are disjoint -> no ordering needed between the branches.
    cudaEventRecord(g_evA, 0);
    cudaStreamWaitEvent(g_s2, g_evA, 0);
    cudaMemsetAsync(out + zero_start, 0, zero_bytes, g_s2);

    head_kernel<<<NROWS_SPECIAL + BATCH, 128>>>(
        g_cd, eig, a_eps, b_eps, (float4*)out, y_off / 4);

    // Join: downstream (and graph end) depends on both branches.
    cudaEventRecord(g_evB, g_s2);
    cudaStreamWaitEvent((cudaStream_t)0, g_evB, 0);
}

// round 14
// speedup vs baseline: 1.4810x; 1.0081x over previous
#include <cuda_runtime.h>
#include <cmath>
#include <vector>
#include <cstddef>

// Problem dimensions
#define LAT 512
#define BATCH 128
#define NROWS_SPECIAL 639   // rows 0..638 of bc contain all nonzero entries

// Constants computed on the host once (input-independent):
//   ddr[l] = Re( DFT_diag[l] * diag(inv(DFT))[l] )
//   dq[l]  = DFT_diag[l]  (entries in {-1,0,1} + i{-1,0,1})
struct ConstData {
    float ddr[LAT];
    float2 dq[LAT];
};

static ConstData g_cd;

// Side stream + events for the fork-join capture pattern. Created once at
// program load (host-side; no device allocations inside kernel_launch).
static cudaStream_t g_s2;
static cudaEvent_t g_evA, g_evB;
static struct StreamInit {
    StreamInit() {
        cudaStreamCreateWithFlags(&g_s2, cudaStreamNonBlocking);
        cudaEventCreateWithFlags(&g_evA, cudaEventDisableTiming);
        cudaEventCreateWithFlags(&g_evB, cudaEventDisableTiming);
    }
} g_sinit;

// ---------------------------------------------------------------------------
// Host-side static init: build the rounded DFT matrix, LU-factorize in double
// precision, extract diag(inv(M)). Pure CPU, once at load, off the timed path.
// ---------------------------------------------------------------------------
static struct ConstInit {
    ConstInit() {
        const int L = LAT;
        std::vector<double> Ar((size_t)L * L), Ai((size_t)L * L);
        std::vector<double> dgr(L), dgi(L);
        const double TWO_PI = 6.283185307179586476925286766559;
        for (int j = 0; j < L; j++) {
            for (int k = 0; k < L; k++) {
                int m = (j * k) % L;
                double ang = TWO_PI * (double)m / (double)L;
                Ar[(size_t)j * L + k] = std::round(std::cos(ang));
                Ai[(size_t)j * L + k] = std::round(std::sin(ang));
            }
            dgr[j] = Ar[(size_t)j * L + j];
            dgi[j] = Ai[(size_t)j * L + j];
        }

        // LU with partial pivoting (in place)
        std::vector<int> piv(L);
        for (int k = 0; k < L; k++) {
            int p = k;
            double best = Ar[(size_t)k * L + k] * Ar[(size_t)k * L + k] +
                          Ai[(size_t)k * L + k] * Ai[(size_t)k * L + k];
            for (int i = k + 1; i < L; i++) {
                double v = Ar[(size_t)i * L + k] * Ar[(size_t)i * L + k] +
                           Ai[(size_t)i * L + k] * Ai[(size_t)i * L + k];
                if (v > best) { best = v; p = i; }
            }
            piv[k] = p;
            if (p != k) {
                for (int j = 0; j < L; j++) {
                    double tr = Ar[(size_t)k * L + j], ti = Ai[(size_t)k * L + j];
                    Ar[(size_t)k * L + j] = Ar[(size_t)p * L + j];
                    Ai[(size_t)k * L + j] = Ai[(size_t)p * L + j];
                    Ar[(size_t)p * L + j] = tr;
                    Ai[(size_t)p * L + j] = ti;
                }
            }
            double akr = Ar[(size_t)k * L + k], aki = Ai[(size_t)k * L + k];
            double den = 1.0 / (akr * akr + aki * aki);
            const double* rkr = &Ar[(size_t)k * L];
            const double* rki = &Ai[(size_t)k * L];
            for (int i = k + 1; i < L; i++) {
                double* rir = &Ar[(size_t)i * L];
                double* rii = &Ai[(size_t)i * L];
                double xr = rir[k], xi = rii[k];
                double fr = (xr * akr + xi * aki) * den;
                double fi = (xi * akr - xr * aki) * den;
                rir[k] = fr; rii[k] = fi;
                for (int j = k + 1; j < L; j++) {
                    double br = rkr[j], bi = rki[j];
                    rir[j] -= fr * br - fi * bi;
                    rii[j] -= fr * bi + fi * br;
                }
            }
        }

        // diag(inv(M)): for each column c, solve M x = e_c, keep x[c]
        std::vector<double> xr(L), xi(L);
        for (int c = 0; c < L; c++) {
            for (int i = 0; i < L; i++) { xr[i] = (i == c) ? 1.0 : 0.0; xi[i] = 0.0; }
            for (int k = 0; k < L; k++) {
                if (piv[k] != k) {
                    double tr = xr[k], ti = xi[k];
                    xr[k] = xr[piv[k]]; xi[k] = xi[piv[k]];
                    xr[piv[k]] = tr;    xi[piv[k]] = ti;
                }
            }
            for (int i = 0; i < L; i++) {          // forward solve (unit lower)
                double sr = xr[i], si = xi[i];
                const double* rir = &Ar[(size_t)i * L];
                const double* rii = &Ai[(size_t)i * L];
                for (int j = 0; j < i; j++) {
                    sr -= rir[j] * xr[j] - rii[j] * xi[j];
                    si -= rir[j] * xi[j] + rii[j] * xr[j];
                }
                xr[i] = sr; xi[i] = si;
            }
            for (int i = L - 1; i >= 0; i--) {     // back solve
                double sr = xr[i], si = xi[i];
                const double* rir = &Ar[(size_t)i * L];
                const double* rii = &Ai[(size_t)i * L];
                for (int j = i + 1; j < L; j++) {
                    sr -= rir[j] * xr[j] - rii[j] * xi[j];
                    si -= rir[j] * xi[j] + rii[j] * xr[j];
                }
                double ur = rir[i], ui = rii[i];
                double den = 1.0 / (ur * ur + ui * ui);
                xr[i] = (sr * ur + si * ui) * den;
                xi[i] = (si * ur - sr * ui) * den;
            }
            // Re(dd[c]) = Re( diag[c] * dinv_diag[c] )
            g_cd.ddr[c] = (float)(dgr[c] * xr[c] - dgi[c] * xi[c]);
            g_cd.dq[c] = make_float2((float)dgr[c], (float)dgi[c]);
        }
    }
} g_init;

// ---------------------------------------------------------------------------
// Small kernel (runs CONCURRENTLY with the big memset; disjoint regions):
//   blocks 0..638   : write bc row r completely (zeros + its nonzero entry)
//   blocks 639..766 : write Y row b = blk-639
// One block per 512-float row; thread t owns float4 #t of the row.
// ---------------------------------------------------------------------------
__global__ void __launch_bounds__(128)
head_kernel(ConstData cd,
            const float* __restrict__ eig,
            const float* __restrict__ a_eps,
            const float* __restrict__ b_eps,
            float4* __restrict__ out4,
            size_t y4_off) {
    const int t = threadIdx.x;       // 0..127
    const int blk = blockIdx.x;      // 0..766
    const float* __restrict__ e127p = eig + (BATCH - 1) * LAT;

    if (blk < NROWS_SPECIAL) {
        float4 v = make_float4(0.f, 0.f, 0.f, 0.f);
        if (blk < BATCH - 1) {
            // Re(bc)[blk, 0] = ddr[0] * eig[blk, 0]
            if (t == 0) v.x = cd.ddr[0] * eig[blk * LAT];
        } else {
            // Re(bc)[127 + d, d] = ddr[d] * eig[127, d]
            const int d = blk - (BATCH - 1);
            if ((d >> 2) == t) {
                const float val = cd.ddr[d] * e127p[d];
                ((float*)&v)[d & 3] = val;
            }
        }
        out4[(size_t)blk * 128 + t] = v;
    } else {
        const int b = blk - NROWS_SPECIAL;   // 0..127
        const int l0 = t << 2;
        float4 v;
        #pragma unroll
        for (int k = 0; k < 4; k++) {
            const int l = l0 + k;
            const float2 q = cd.dq[l];
            ((float*)&v)[k] = sqrtf(e127p[l]) *
                (q.x * a_eps[l * BATCH + b] - q.y * b_eps[l * BATCH + b]);
        }
        out4[y4_off + (size_t)b * 128 + t] = v;
    }
}

extern "C" void kernel_launch(void* const* d_in, const int* in_sizes, int n_in,
                              void* d_out, int out_size) {
    const float* eig   = (const float*)d_in[0];  // eigenvalues (128, 512)
    const float* a_eps = (const float*)d_in[1];  // (512, 128)
    const float* b_eps = (const float*)d_in[2];  // (512, 128)
    float* out = (float*)d_out;

    // out_size = 33,619,968 float32 elements:
    //   [ Re(bc) : 65536*512 = 33,554,432 ][ Y : 128*512 = 65,536 ]
    const size_t y_floats = (size_t)BATCH * LAT;            // 65536
    const size_t y_off = (size_t)out_size - y_floats;       // 33,554,432
    const size_t zero_start = (size_t)NROWS_SPECIAL * LAT;  // 327,168 floats
    const size_t zero_bytes = (y_off - zero_start) * sizeof(float);  // ~132.9 MB

    // Fork: branch A (side stream) zeros rows 639.. (pure zeros, peak BW);
    //       branch B (capture stream) writes rows 0..638 + Y concurrently.
    // Regions are disjoint -> no ordering needed between the branches.
    cudaEventRecord(g_evA, 0);
    cudaStreamWaitEvent(g_s2, g_evA, 0);
    cudaMemsetAsync(out + zero_start, 0, zero_bytes, g_s2);

    head_kernel<<<NROWS_SPECIAL + BATCH, 128>>>(
        g_cd, eig, a_eps, b_eps, (float4*)out, y_off / 4);

    // Join: downstream (and graph end) depends on both branches.
    cudaEventRecord(g_evB, g_s2);
    cudaStreamWaitEvent((cudaStream_t)0, g_evB, 0);
}

// round 16
// speedup vs baseline: 1.5396x; 1.0396x over previous
#include <cuda_runtime.h>
#include <cmath>
#include <vector>
#include <cstddef>

// Problem dimensions
#define LAT 512
#define BATCH 128
#define NROWS_SPECIAL 639   // rows 0..638 of bc contain all nonzero entries

// Constants computed on the host once (input-independent):
//   ddr[l] = Re( DFT_diag[l] * diag(inv(DFT))[l] )
//   dq[l]  = DFT_diag[l]  (entries in {-1,0,1} + i{-1,0,1})
struct ConstData {
    float ddr[LAT];
    float2 dq[LAT];
};

static ConstData g_cd;

// Side stream + events for the fork-join capture pattern. Created once at
// program load (host-side; no device allocations inside kernel_launch).
static cudaStream_t g_s2;
static cudaEvent_t g_evA, g_evB;
static struct StreamInit {
    StreamInit() {
        cudaStreamCreateWithFlags(&g_s2, cudaStreamNonBlocking);
        cudaEventCreateWithFlags(&g_evA, cudaEventDisableTiming);
        cudaEventCreateWithFlags(&g_evB, cudaEventDisableTiming);
    }
} g_sinit;

// ---------------------------------------------------------------------------
// Host-side static init: build the rounded DFT matrix, LU-factorize in double
// precision, extract diag(inv(M)). Pure CPU, once at load, off the timed path.
// ---------------------------------------------------------------------------
static struct ConstInit {
    ConstInit() {
        const int L = LAT;
        std::vector<double> Ar((size_t)L * L), Ai((size_t)L * L);
        std::vector<double> dgr(L), dgi(L);
        const double TWO_PI = 6.283185307179586476925286766559;
        for (int j = 0; j < L; j++) {
            for (int k = 0; k < L; k++) {
                int m = (j * k) % L;
                double ang = TWO_PI * (double)m / (double)L;
                Ar[(size_t)j * L + k] = std::round(std::cos(ang));
                Ai[(size_t)j * L + k] = std::round(std::sin(ang));
            }
            dgr[j] = Ar[(size_t)j * L + j];
            dgi[j] = Ai[(size_t)j * L + j];
        }

        // LU with partial pivoting (in place)
        std::vector<int> piv(L);
        for (int k = 0; k < L; k++) {
            int p = k;
            double best = Ar[(size_t)k * L + k] * Ar[(size_t)k * L + k] +
                          Ai[(size_t)k * L + k] * Ai[(size_t)k * L + k];
            for (int i = k + 1; i < L; i++) {
                double v = Ar[(size_t)i * L + k] * Ar[(size_t)i * L + k] +
                           Ai[(size_t)i * L + k] * Ai[(size_t)i * L + k];
                if (v > best) { best = v; p = i; }
            }
            piv[k] = p;
            if (p != k) {
                for (int j = 0; j < L; j++) {
                    double tr = Ar[(size_t)k * L + j], ti = Ai[(size_t)k * L + j];
                    Ar[(size_t)k * L + j] = Ar[(size_t)p * L + j];
                    Ai[(size_t)k * L + j] = Ai[(size_t)p * L + j];
                    Ar[(size_t)p * L + j] = tr;
                    Ai[(size_t)p * L + j] = ti;
                }
            }
            double akr = Ar[(size_t)k * L + k], aki = Ai[(size_t)k * L + k];
            double den = 1.0 / (akr * akr + aki * aki);
            const double* rkr = &Ar[(size_t)k * L];
            const double* rki = &Ai[(size_t)k * L];
            for (int i = k + 1; i < L; i++) {
                double* rir = &Ar[(size_t)i * L];
                double* rii = &Ai[(size_t)i * L];
                double xr = rir[k], xi = rii[k];
                double fr = (xr * akr + xi * aki) * den;
                double fi = (xi * akr - xr * aki) * den;
                rir[k] = fr; rii[k] = fi;
                for (int j = k + 1; j < L; j++) {
                    double br = rkr[j], bi = rki[j];
                    rir[j] -= fr * br - fi * bi;
                    rii[j] -= fr * bi + fi * br;
                }
            }
        }

        // diag(inv(M)): for each column c, solve M x = e_c, keep x[c]
        std::vector<double> xr(L), xi(L);
        for (int c = 0; c < L; c++) {
            for (int i = 0; i < L; i++) { xr[i] = (i == c) ? 1.0 : 0.0; xi[i] = 0.0; }
            for (int k = 0; k < L; k++) {
                if (piv[k] != k) {
                    double tr = xr[k], ti = xi[k];
                    xr[k] = xr[piv[k]]; xi[k] = xi[piv[k]];
                    xr[piv[k]] = tr;    xi[piv[k]] = ti;
                }
            }
            for (int i = 0; i < L; i++) {          // forward solve (unit lower)
                double sr = xr[i], si = xi[i];
                const double* rir = &Ar[(size_t)i * L];
                const double* rii = &Ai[(size_t)i * L];
                for (int j = 0; j < i; j++) {
                    sr -= rir[j] * xr[j] - rii[j] * xi[j];
                    si -= rir[j] * xi[j] + rii[j] * xr[j];
                }
                xr[i] = sr; xi[i] = si;
            }
            for (int i = L - 1; i >= 0; i--) {     // back solve
                double sr = xr[i], si = xi[i];
                const double* rir = &Ar[(size_t)i * L];
                const double* rii = &Ai[(size_t)i * L];
                for (int j = i + 1; j < L; j++) {
                    sr -= rir[j] * xr[j] - rii[j] * xi[j];
                    si -= rir[j] * xi[j] + rii[j] * xr[j];
                }
                double ur = rir[i], ui = rii[i];
                double den = 1.0 / (ur * ur + ui * ui);
                xr[i] = (sr * ur + si * ui) * den;
                xi[i] = (si * ur - sr * ui) * den;
            }
            // Re(dd[c]) = Re( diag[c] * dinv_diag[c] )
            g_cd.ddr[c] = (float)(dgr[c] * xr[c] - dgi[c] * xi[c]);
            g_cd.dq[c] = make_float2((float)dgr[c], (float)dgi[c]);
        }
    }
} g_init;

// ---------------------------------------------------------------------------
// Small kernel (runs CONCURRENTLY with the big memset; disjoint regions):
//   blocks 0..638   : write bc row r completely (zeros + its nonzero entry)
//   blocks 639..766 : write Y row b = blk-639
// One block per 512-float row; thread t owns float4 #t of the row.
// ---------------------------------------------------------------------------
__global__ void __launch_bounds__(128)
head_kernel(ConstData cd,
            const float* __restrict__ eig,
            const float* __restrict__ a_eps,
            const float* __restrict__ b_eps,
            float4* __restrict__ out4,
            size_t y4_off) {
    const int t = threadIdx.x;       // 0..127
    const int blk = blockIdx.x;      // 0..766
    const float* __restrict__ e127p = eig + (BATCH - 1) * LAT;

    if (blk < NROWS_SPECIAL) {
        float4 v = make_float4(0.f, 0.f, 0.f, 0.f);
        if (blk < BATCH - 1) {
            // Re(bc)[blk, 0] = ddr[0] * eig[blk, 0]
            if (t == 0) v.x = cd.ddr[0] * eig[blk * LAT];
        } else {
            // Re(bc)[127 + d, d] = ddr[d] * eig[127, d]
            const int d = blk - (BATCH - 1);
            if ((d >> 2) == t) {
                const float val = cd.ddr[d] * e127p[d];
                ((float*)&v)[d & 3] = val;
            }
        }
        out4[(size_t)blk * 128 + t] = v;
    } else {
        const int b = blk - NROWS_SPECIAL;   // 0..127
        const int l0 = t << 2;
        float4 v;
        #pragma unroll
        for (int k = 0; k < 4; k++) {
            const int l = l0 + k;
            const float2 q = cd.dq[l];
            ((float*)&v)[k] = sqrtf(e127p[l]) *
                (q.x * a_eps[l * BATCH + b] - q.y * b_eps[l * BATCH + b]);
        }
        out4[y4_off + (size_t)b * 128 + t] = v;
    }
}

extern "C" void kernel_launch(void* const* d_in, const int* in_sizes, int n_in,
                              void* d_out, int out_size) {
    const float* eig   = (const float*)d_in[0];  // eigenvalues (128, 512)
    const float* a_eps = (const float*)d_in[1];  // (512, 128)
    const float* b_eps = (const float*)d_in[2];  // (512, 128)
    float* out = (float*)d_out;

    // out_size = 33,619,968 float32 elements:
    //   [ Re(bc) : 65536*512 = 33,554,432 ][ Y : 128*512 = 65,536 ]
    const size_t y_floats = (size_t)BATCH * LAT;            // 65536
    const size_t y_off = (size_t)out_size - y_floats;       // 33,554,432
    const size_t zero_start = (size_t)NROWS_SPECIAL * LAT;  // 327,168 floats
    const size_t zero_bytes = (y_off - zero_start) * sizeof(float);  // ~132.9 MB

    // Fork: branch A (side stream) zeros rows 639.. (pure zeros, peak BW);
    //       branch B (capture stream) writes rows 0..638 + Y concurrently.
    // Regions are disjoint -> no ordering needed between the branches.
    cudaEventRecord(g_evA, 0);
    cudaStreamWaitEvent(g_s2, g_evA, 0);
    cudaMemsetAsync(out + zero_start, 0, zero_bytes, g_s2);

    head_kernel<<<NROWS_SPECIAL + BATCH, 128>>>(
        g_cd, eig, a_eps, b_eps, (float4*)out, y_off / 4);

    // Join: downstream (and graph end) depends on both branches.
    cudaEventRecord(g_evB, g_s2);
    cudaStreamWaitEvent((cudaStream_t)0, g_evB, 0);
}